// round 5
// baseline (speedup 1.0000x reference)
#include <cuda_runtime.h>
#include <cstdint>
#include <cstddef>

#define N_NODES 50000
#define E_EDGES 400000
#define IN_DIM  384
#define HID     256
#define QDIM    384
#define HHID    128

// ---------------- scratch (static device globals; float4 => 16B aligned) -----
__device__ float  g_deg[N_NODES];                            // 1/(deg+1)
__device__ float4 g_agg[(size_t)N_NODES * IN_DIM / 4];       // widest agg buffer
__device__ float4 g_h1 [(size_t)N_NODES * HID / 4];
__device__ float4 g_h2 [(size_t)N_NODES * HID / 4];
__device__ float4 g_s  [(size_t)N_NODES * HHID / 4];
__device__ float  g_qb1[HID];
__device__ float  g_qb2[HID];
__device__ float  g_qbh[HHID];
__device__ int    g_is64;
__device__ int    g_src[E_EDGES];
__device__ int    g_dst[E_EDGES];

// ---------------- edge-index dtype sniffing + conversion ---------------------
// If edge_index is int64 (values < 2^31), every odd 32-bit word is 0.
// For int32 data, 128 consecutive odd words all being 0 is ~impossible.
__global__ void detect_idx_dtype(const int* __restrict__ raw) {
    int nz = 0;
    for (int i = threadIdx.x; i < 128; i += 32)
        if (raw[2 * i + 1] != 0) nz = 1;
    #pragma unroll
    for (int o = 16; o > 0; o >>= 1) nz |= __shfl_xor_sync(0xffffffffu, nz, o);
    if (threadIdx.x == 0) g_is64 = nz ? 0 : 1;
}

__global__ void convert_idx(const void* __restrict__ raw, int E) {
    int i = blockIdx.x * blockDim.x + threadIdx.x;
    if (i >= 2 * E) return;
    int v;
    if (g_is64) v = (int)((const long long*)raw)[i];
    else        v = ((const int*)raw)[i];
    if ((unsigned)v >= (unsigned)N_NODES) v = 0;   // defensive clamp
    if (i < E) g_src[i] = v;
    else       g_dst[i - E] = v;
}

// ---------------- small utility kernels --------------------------------------
__global__ void zero_deg(int n) {
    int i = blockIdx.x * blockDim.x + threadIdx.x;
    if (i < n) g_deg[i] = 0.f;
}

__global__ void count_deg(int E) {
    int e = blockIdx.x * blockDim.x + threadIdx.x;
    if (e < E) atomicAdd(&g_deg[g_dst[e]], 1.f);
}

__global__ void finalize_deg(int n) {
    int i = blockIdx.x * blockDim.x + threadIdx.x;
    if (i < n) g_deg[i] = 1.f / (g_deg[i] + 1.f);
}

__global__ void copy_to_agg(const float4* __restrict__ src, size_t n) {
    size_t i = (size_t)blockIdx.x * blockDim.x + threadIdx.x;
    if (i < n) g_agg[i] = src[i];
}

// vector float4 reduction into global memory (sm_90+)
__device__ __forceinline__ void red_add_f4(float4* addr, float4 v) {
    asm volatile("red.global.add.v4.f32 [%0], {%1,%2,%3,%4};"
                 :: "l"(addr), "f"(v.x), "f"(v.y), "f"(v.z), "f"(v.w)
                 : "memory");
}

// one warp per edge: g_agg[dst] += feat[src]   (D4 = feature dim / 4)
__global__ void scatter_add(const float4* __restrict__ feat, int E, int D4) {
    int warp = (blockIdx.x * blockDim.x + threadIdx.x) >> 5;
    int lane = threadIdx.x & 31;
    if (warp >= E) return;
    int s = g_src[warp];
    int d = g_dst[warp];
    const float4* sp = feat  + (size_t)s * D4;
    float4*       dp = g_agg + (size_t)d * D4;
    for (int i = lane; i < D4; i += 32) {
        red_add_f4(dp + i, sp[i]);
    }
}

// qb[j] = b[j] + sum_k q[k] * W[(qoff+k)*N + j]
__global__ void qproj(const float* __restrict__ q, const float* __restrict__ W,
                      const float* __restrict__ b, float* __restrict__ qb,
                      int qoff, int qdim, int N) {
    int j = blockIdx.x * blockDim.x + threadIdx.x;
    if (j >= N) return;
    float acc = b[j];
    for (int k = 0; k < qdim; ++k)
        acc = fmaf(q[k], W[(size_t)(qoff + k) * N + j], acc);
    qb[j] = acc;
}

// ---------------- fused concat GEMM + bias(q-folded) + relu ------------------
// out[i,j] = relu( [A1_i , rscale_i * A2_i] @ W[0:K1+K2] + qb[j] )
// BM=64, BN=64, BK=16, 256 threads, 4x4 per thread. K1,K2 multiples of 16.
#define BM 64
#define BN 64
#define BK 16

template<int K1, int K2, bool RELU>
__global__ __launch_bounds__(256)
void gemm_cat(const float* __restrict__ A1,
              const float* __restrict__ A2,
              const float* __restrict__ rscale,
              const float* __restrict__ W,
              const float* __restrict__ qb,
              float* __restrict__ out,
              int M, int N)
{
    __shared__ float As[BK][BM + 1];
    __shared__ float Bs[BK][BN];

    const int tid = threadIdx.x;
    const int block_row = blockIdx.x * BM;
    const int block_col = blockIdx.y * BN;

    // A-load mapping: 64 rows x 16 k, 4 consecutive k per thread
    const int ar  = tid >> 2;            // 0..63
    const int ak  = (tid & 3) * 4;       // 0,4,8,12
    const int arow = block_row + ar;
    const bool arow_ok = arow < M;
    float rs = 1.f;
    if (K2 > 0 && arow_ok) rs = rscale[arow];

    // B-load mapping: 16 k x 64 cols, 4 consecutive cols per thread
    const int bk = tid >> 4;             // 0..15
    const int bc = (tid & 15) * 4;       // 0..60

    const int tx = tid & 15;             // col group
    const int ty = tid >> 4;             // row group

    float acc[4][4] = {};

    const int KTOT = K1 + K2;
    for (int kt = 0; kt < KTOT; kt += BK) {
        float4 av = make_float4(0.f, 0.f, 0.f, 0.f);
        if (arow_ok) {
            if (kt < K1) {
                av = *(const float4*)(A1 + (size_t)arow * K1 + kt + ak);
            } else {
                av = *(const float4*)(A2 + (size_t)arow * K2 + (kt - K1) + ak);
                av.x *= rs; av.y *= rs; av.z *= rs; av.w *= rs;
            }
        }
        As[ak + 0][ar] = av.x;
        As[ak + 1][ar] = av.y;
        As[ak + 2][ar] = av.z;
        As[ak + 3][ar] = av.w;

        float4 bv = *(const float4*)(W + (size_t)(kt + bk) * N + block_col + bc);
        *(float4*)&Bs[bk][bc] = bv;

        __syncthreads();

        #pragma unroll
        for (int k = 0; k < BK; ++k) {
            float a0 = As[k][ty * 4 + 0];
            float a1 = As[k][ty * 4 + 1];
            float a2 = As[k][ty * 4 + 2];
            float a3 = As[k][ty * 4 + 3];
            float b0 = Bs[k][tx * 4 + 0];
            float b1 = Bs[k][tx * 4 + 1];
            float b2 = Bs[k][tx * 4 + 2];
            float b3 = Bs[k][tx * 4 + 3];
            acc[0][0] = fmaf(a0, b0, acc[0][0]); acc[0][1] = fmaf(a0, b1, acc[0][1]);
            acc[0][2] = fmaf(a0, b2, acc[0][2]); acc[0][3] = fmaf(a0, b3, acc[0][3]);
            acc[1][0] = fmaf(a1, b0, acc[1][0]); acc[1][1] = fmaf(a1, b1, acc[1][1]);
            acc[1][2] = fmaf(a1, b2, acc[1][2]); acc[1][3] = fmaf(a1, b3, acc[1][3]);
            acc[2][0] = fmaf(a2, b0, acc[2][0]); acc[2][1] = fmaf(a2, b1, acc[2][1]);
            acc[2][2] = fmaf(a2, b2, acc[2][2]); acc[2][3] = fmaf(a2, b3, acc[2][3]);
            acc[3][0] = fmaf(a3, b0, acc[3][0]); acc[3][1] = fmaf(a3, b1, acc[3][1]);
            acc[3][2] = fmaf(a3, b2, acc[3][2]); acc[3][3] = fmaf(a3, b3, acc[3][3]);
        }
        __syncthreads();
    }

    #pragma unroll
    for (int i = 0; i < 4; ++i) {
        int row = block_row + ty * 4 + i;
        if (row < M) {
            #pragma unroll
            for (int j = 0; j < 4; ++j) {
                int col = block_col + tx * 4 + j;
                float v = acc[i][j] + qb[col];
                if (RELU) v = fmaxf(v, 0.f);
                out[(size_t)row * N + col] = v;
            }
        }
    }
}

// logits[i] = bh2 + sum_j s[i][j] * Wh2[j]   (one warp per node, 128 = 32*float4)
__global__ void head_dot(const float* __restrict__ Wh2,
                         const float* __restrict__ bh2, float* __restrict__ out, int M) {
    int warp = (blockIdx.x * blockDim.x + threadIdx.x) >> 5;
    int lane = threadIdx.x & 31;
    if (warp >= M) return;
    float4 a = g_s[(size_t)warp * (HHID / 4) + lane];
    float b0 = Wh2[lane * 4 + 0], b1 = Wh2[lane * 4 + 1];
    float b2 = Wh2[lane * 4 + 2], b3 = Wh2[lane * 4 + 3];
    float v = a.x * b0 + a.y * b1 + a.z * b2 + a.w * b3;
    #pragma unroll
    for (int o = 16; o > 0; o >>= 1) v += __shfl_xor_sync(0xffffffffu, v, o);
    if (lane == 0) out[warp] = v + bh2[0];
}

// ---------------- launch -----------------------------------------------------
extern "C" void kernel_launch(void* const* d_in, const int* in_sizes, int n_in,
                              void* d_out, int out_size)
{
    const float* x   = (const float*)d_in[0];
    const void*  ei  = d_in[1];                 // int32 or int64 — sniffed on device
    const float* q   = (const float*)d_in[2];
    const float* W1  = (const float*)d_in[3];
    const float* b1  = (const float*)d_in[4];
    const float* W2  = (const float*)d_in[5];
    const float* b2  = (const float*)d_in[6];
    const float* Wh1 = (const float*)d_in[7];
    const float* bh1 = (const float*)d_in[8];
    const float* Wh2 = (const float*)d_in[9];
    const float* bh2 = (const float*)d_in[10];
    float* out = (float*)d_out;

    const int M = in_sizes[0] / IN_DIM;   // 50000
    const int E = in_sizes[1] / 2;        // 400000

    float  *p_deg, *p_qb1, *p_qb2, *p_qbh;
    float4 *p_agg, *p_h1, *p_h2, *p_s;
    cudaGetSymbolAddress((void**)&p_deg, g_deg);
    cudaGetSymbolAddress((void**)&p_agg, g_agg);
    cudaGetSymbolAddress((void**)&p_h1,  g_h1);
    cudaGetSymbolAddress((void**)&p_h2,  g_h2);
    cudaGetSymbolAddress((void**)&p_s,   g_s);
    cudaGetSymbolAddress((void**)&p_qb1, g_qb1);
    cudaGetSymbolAddress((void**)&p_qb2, g_qb2);
    cudaGetSymbolAddress((void**)&p_qbh, g_qbh);

    // edge index: sniff dtype, unpack to int32 src/dst
    detect_idx_dtype<<<1, 32>>>((const int*)ei);
    convert_idx<<<(2 * E + 255) / 256, 256>>>(ei, E);

    // degree -> 1/(deg+1)
    zero_deg    <<<(M + 255) / 256, 256>>>(M);
    count_deg   <<<(E + 255) / 256, 256>>>(E);
    finalize_deg<<<(M + 255) / 256, 256>>>(M);

    // ---- layer 1 ----
    copy_to_agg<<<(int)(((size_t)M * IN_DIM / 4 + 255) / 256), 256>>>(
        (const float4*)x, (size_t)M * IN_DIM / 4);
    scatter_add<<<(E + 7) / 8, 256>>>((const float4*)x, E, IN_DIM / 4);
    qproj<<<1, 256>>>(q, W1, b1, p_qb1, 2 * IN_DIM, QDIM, HID);
    {
        dim3 g((M + BM - 1) / BM, HID / BN);
        gemm_cat<IN_DIM, IN_DIM, true><<<g, 256>>>(x, (const float*)p_agg, p_deg,
                                                   W1, p_qb1, (float*)p_h1, M, HID);
    }

    // ---- layer 2 ----
    copy_to_agg<<<(int)(((size_t)M * HID / 4 + 255) / 256), 256>>>(
        (const float4*)p_h1, (size_t)M * HID / 4);
    scatter_add<<<(E + 7) / 8, 256>>>((const float4*)p_h1, E, HID / 4);
    qproj<<<1, 256>>>(q, W2, b2, p_qb2, 2 * HID, QDIM, HID);
    {
        dim3 g((M + BM - 1) / BM, HID / BN);
        gemm_cat<HID, HID, true><<<g, 256>>>((const float*)p_h1, (const float*)p_agg, p_deg,
                                             W2, p_qb2, (float*)p_h2, M, HID);
    }

    // ---- head ----
    qproj<<<1, 128>>>(q, Wh1, bh1, p_qbh, HID, QDIM, HHID);
    {
        dim3 g((M + BM - 1) / BM, HHID / BN);
        gemm_cat<HID, 0, true><<<g, 256>>>((const float*)p_h2, nullptr, nullptr,
                                           Wh1, p_qbh, (float*)p_s, M, HHID);
    }
    head_dot<<<(M * 32 + 255) / 256, 256>>>(Wh2, bh2, out, M);
}

// round 8
// speedup vs baseline: 2.3576x; 2.3576x over previous
#include <cuda_runtime.h>
#include <cuda_bf16.h>
#include <cstdint>
#include <cstddef>

#define N_NODES 50000
#define E_EDGES 400000
#define IN_DIM  384
#define HID     256
#define QDIM    384
#define HHID    128

// ---------------- scratch (static device globals) ----------------------------
__device__ float  g_deg[N_NODES];                            // 1/(deg+1)
__device__ float4 g_agg[(size_t)N_NODES * IN_DIM / 4];
__device__ float4 g_h1 [(size_t)N_NODES * HID / 4];
__device__ float4 g_h2 [(size_t)N_NODES * HID / 4];
__device__ float4 g_s  [(size_t)N_NODES * HHID / 4];
__device__ float  g_qb1[HID];
__device__ float  g_qb2[HID];
__device__ float  g_qbh[HHID];
__device__ int    g_is64;
__device__ int    g_src[E_EDGES];
__device__ int    g_dst[E_EDGES];

// ---------------- edge-index dtype sniffing + conversion ---------------------
__global__ void detect_idx_dtype(const int* __restrict__ raw) {
    int nz = 0;
    for (int i = threadIdx.x; i < 128; i += 32)
        if (raw[2 * i + 1] != 0) nz = 1;
    #pragma unroll
    for (int o = 16; o > 0; o >>= 1) nz |= __shfl_xor_sync(0xffffffffu, nz, o);
    if (threadIdx.x == 0) g_is64 = nz ? 0 : 1;
}

__global__ void convert_idx(const void* __restrict__ raw, int E) {
    int i = blockIdx.x * blockDim.x + threadIdx.x;
    if (i >= 2 * E) return;
    int v;
    if (g_is64) v = (int)((const long long*)raw)[i];
    else        v = ((const int*)raw)[i];
    if ((unsigned)v >= (unsigned)N_NODES) v = 0;
    if (i < E) g_src[i] = v;
    else       g_dst[i - E] = v;
}

// ---------------- small utility kernels --------------------------------------
__global__ void zero_deg(int n) {
    int i = blockIdx.x * blockDim.x + threadIdx.x;
    if (i < n) g_deg[i] = 0.f;
}
__global__ void count_deg(int E) {
    int e = blockIdx.x * blockDim.x + threadIdx.x;
    if (e < E) atomicAdd(&g_deg[g_dst[e]], 1.f);
}
__global__ void finalize_deg(int n) {
    int i = blockIdx.x * blockDim.x + threadIdx.x;
    if (i < n) g_deg[i] = 1.f / (g_deg[i] + 1.f);
}
__global__ void copy_to_agg(const float4* __restrict__ src, size_t n) {
    size_t i = (size_t)blockIdx.x * blockDim.x + threadIdx.x;
    if (i < n) g_agg[i] = src[i];
}

__device__ __forceinline__ void red_add_f4(float4* addr, float4 v) {
    asm volatile("red.global.add.v4.f32 [%0], {%1,%2,%3,%4};"
                 :: "l"(addr), "f"(v.x), "f"(v.y), "f"(v.z), "f"(v.w)
                 : "memory");
}

// one warp per edge: g_agg[dst] += feat[src]
__global__ void scatter_add(const float4* __restrict__ feat, int E, int D4) {
    int warp = (blockIdx.x * blockDim.x + threadIdx.x) >> 5;
    int lane = threadIdx.x & 31;
    if (warp >= E) return;
    int s = g_src[warp];
    int d = g_dst[warp];
    const float4* sp = feat  + (size_t)s * D4;
    float4*       dp = g_agg + (size_t)d * D4;
    for (int i = lane; i < D4; i += 32) red_add_f4(dp + i, sp[i]);
}

// qb[j] = b[j] + sum_k q[k] * W[(qoff+k)*N + j]
__global__ void qproj(const float* __restrict__ q, const float* __restrict__ W,
                      const float* __restrict__ b, float* __restrict__ qb,
                      int qoff, int qdim, int N) {
    int j = blockIdx.x * blockDim.x + threadIdx.x;
    if (j >= N) return;
    float acc = b[j];
    for (int k = 0; k < qdim; ++k)
        acc = fmaf(q[k], W[(size_t)(qoff + k) * N + j], acc);
    qb[j] = acc;
}

// ---------------- tensor-core concat GEMM (bf16x3 split) ---------------------
// out[i,j] = relu([A1_i, rs_i*A2_i] @ W + qb[j]); fp32 in/out, bf16 hi+lo mma.
// Block 128x64, 8 warps (4m x 2n), warp tile 32x32, m16n8k16, BK=32.

__device__ __forceinline__ void mma16816(float* d, const unsigned* a, const unsigned* b) {
    asm volatile("mma.sync.aligned.m16n8k16.row.col.f32.bf16.bf16.f32 "
                 "{%0,%1,%2,%3}, {%4,%5,%6,%7}, {%8,%9}, {%0,%1,%2,%3};"
                 : "+f"(d[0]), "+f"(d[1]), "+f"(d[2]), "+f"(d[3])
                 : "r"(a[0]), "r"(a[1]), "r"(a[2]), "r"(a[3]),
                   "r"(b[0]), "r"(b[1]));
}

__device__ __forceinline__ void split2(float x0, float x1, unsigned& hp, unsigned& lp) {
    __nv_bfloat16 h0 = __float2bfloat16_rn(x0);
    __nv_bfloat16 h1 = __float2bfloat16_rn(x1);
    __nv_bfloat16 l0 = __float2bfloat16_rn(x0 - __bfloat162float(h0));
    __nv_bfloat16 l1 = __float2bfloat16_rn(x1 - __bfloat162float(h1));
    hp = (unsigned)__bfloat16_as_ushort(h0) | ((unsigned)__bfloat16_as_ushort(h1) << 16);
    lp = (unsigned)__bfloat16_as_ushort(l0) | ((unsigned)__bfloat16_as_ushort(l1) << 16);
}

#define TBM 128
#define TBN 64
#define TBK 32
#define SPAD 34   // smem row stride (elements), odd word stride kills conflicts

template<int K1, int K2, int NN>
__global__ __launch_bounds__(256)
void gemm_cat_tc(const float* __restrict__ A1,
                 const float* __restrict__ A2,
                 const float* __restrict__ rscale,
                 const float* __restrict__ W,
                 const float* __restrict__ qb,
                 float* __restrict__ out, int M)
{
    __shared__ unsigned short As_h[TBM][SPAD];
    __shared__ unsigned short As_l[TBM][SPAD];
    __shared__ unsigned short Bs_h[TBN][SPAD];   // transposed: [n][k]
    __shared__ unsigned short Bs_l[TBN][SPAD];

    const int tid  = threadIdx.x;
    const int lane = tid & 31;
    const int wid  = tid >> 5;
    const int wm   = wid & 3;          // 0..3 -> 32-row slice
    const int wn   = wid >> 2;         // 0..1 -> 32-col slice
    const int block_row = blockIdx.x * TBM;
    const int block_col = blockIdx.y * TBN;

    // A loader: 128x32 floats = 1024 float4, 4 per thread
    int a_row[4], a_k[4];
    bool a_ok[4];
    float a_rs[4];
    #pragma unroll
    for (int i = 0; i < 4; ++i) {
        int idx = i * 256 + tid;
        a_row[i] = idx >> 3;           // 0..127
        a_k[i]   = (idx & 7) * 4;      // 0..28
        int gr = block_row + a_row[i];
        a_ok[i] = gr < M;
        a_rs[i] = (K2 > 0 && a_ok[i]) ? rscale[gr] : 1.f;
    }
    // B loader: 32x64 floats = 512 float4, 2 per thread
    int b_k[2], b_n[2];
    #pragma unroll
    for (int i = 0; i < 2; ++i) {
        int idx = i * 256 + tid;
        b_k[i] = idx >> 4;             // 0..31
        b_n[i] = (idx & 15) * 4;       // 0..60
    }

    float4 aF[4], bF[2];
    const int KTOT = K1 + K2;
    const int NSTEP = KTOT / TBK;

    auto loadTiles = [&](int kt) {
        const int kbase = kt * TBK;
        const bool inA1 = kbase < K1;
        #pragma unroll
        for (int i = 0; i < 4; ++i) {
            if (a_ok[i]) {
                int gr = block_row + a_row[i];
                if (inA1) {
                    aF[i] = *(const float4*)(A1 + (size_t)gr * K1 + kbase + a_k[i]);
                } else {
                    float4 v = *(const float4*)(A2 + (size_t)gr * K2 + (kbase - K1) + a_k[i]);
                    float rs = a_rs[i];
                    v.x *= rs; v.y *= rs; v.z *= rs; v.w *= rs;
                    aF[i] = v;
                }
            } else {
                aF[i] = make_float4(0.f, 0.f, 0.f, 0.f);
            }
        }
        #pragma unroll
        for (int i = 0; i < 2; ++i) {
            bF[i] = *(const float4*)(W + (size_t)(kbase + b_k[i]) * NN + block_col + b_n[i]);
        }
    };

    auto storeTiles = [&]() {
        #pragma unroll
        for (int i = 0; i < 4; ++i) {
            unsigned h0, l0, h1, l1;
            split2(aF[i].x, aF[i].y, h0, l0);
            split2(aF[i].z, aF[i].w, h1, l1);
            *(unsigned*)&As_h[a_row[i]][a_k[i]]     = h0;
            *(unsigned*)&As_h[a_row[i]][a_k[i] + 2] = h1;
            *(unsigned*)&As_l[a_row[i]][a_k[i]]     = l0;
            *(unsigned*)&As_l[a_row[i]][a_k[i] + 2] = l1;
        }
        #pragma unroll
        for (int i = 0; i < 2; ++i) {
            float v[4] = {bF[i].x, bF[i].y, bF[i].z, bF[i].w};
            #pragma unroll
            for (int j = 0; j < 4; ++j) {
                __nv_bfloat16 h = __float2bfloat16_rn(v[j]);
                __nv_bfloat16 l = __float2bfloat16_rn(v[j] - __bfloat162float(h));
                Bs_h[b_n[i] + j][b_k[i]] = __bfloat16_as_ushort(h);
                Bs_l[b_n[i] + j][b_k[i]] = __bfloat16_as_ushort(l);
            }
        }
    };

    float acc[2][4][4];
    #pragma unroll
    for (int mt = 0; mt < 2; ++mt)
        #pragma unroll
        for (int nt = 0; nt < 4; ++nt)
            #pragma unroll
            for (int r = 0; r < 4; ++r) acc[mt][nt][r] = 0.f;

    const int grp = lane >> 2;          // 0..7
    const int tig = lane & 3;           // 0..3

    loadTiles(0);
    for (int kt = 0; kt < NSTEP; ++kt) {
        storeTiles();
        __syncthreads();
        if (kt + 1 < NSTEP) loadTiles(kt + 1);

        #pragma unroll
        for (int kk = 0; kk < 2; ++kk) {
            const int c = kk * 16 + tig * 2;
            unsigned ah[2][4], al[2][4], bh[4][2], bl[4][2];
            #pragma unroll
            for (int mt = 0; mt < 2; ++mt) {
                int r = wm * 32 + mt * 16 + grp;
                ah[mt][0] = *(const unsigned*)&As_h[r][c];
                ah[mt][1] = *(const unsigned*)&As_h[r + 8][c];
                ah[mt][2] = *(const unsigned*)&As_h[r][c + 8];
                ah[mt][3] = *(const unsigned*)&As_h[r + 8][c + 8];
                al[mt][0] = *(const unsigned*)&As_l[r][c];
                al[mt][1] = *(const unsigned*)&As_l[r + 8][c];
                al[mt][2] = *(const unsigned*)&As_l[r][c + 8];
                al[mt][3] = *(const unsigned*)&As_l[r + 8][c + 8];
            }
            #pragma unroll
            for (int nt = 0; nt < 4; ++nt) {
                int n = wn * 32 + nt * 8 + grp;
                bh[nt][0] = *(const unsigned*)&Bs_h[n][c];
                bh[nt][1] = *(const unsigned*)&Bs_h[n][c + 8];
                bl[nt][0] = *(const unsigned*)&Bs_l[n][c];
                bl[nt][1] = *(const unsigned*)&Bs_l[n][c + 8];
            }
            #pragma unroll
            for (int mt = 0; mt < 2; ++mt)
                #pragma unroll
                for (int nt = 0; nt < 4; ++nt) {
                    mma16816(acc[mt][nt], ah[mt], bh[nt]);
                    mma16816(acc[mt][nt], ah[mt], bl[nt]);
                    mma16816(acc[mt][nt], al[mt], bh[nt]);
                }
        }
        __syncthreads();
    }

    // epilogue: +qb, relu, store
    #pragma unroll
    for (int mt = 0; mt < 2; ++mt) {
        #pragma unroll
        for (int nt = 0; nt < 4; ++nt) {
            int r0 = block_row + wm * 32 + mt * 16 + grp;
            int c0 = block_col + wn * 32 + nt * 8 + tig * 2;
            float q0 = qb[c0], q1 = qb[c0 + 1];
            if (r0 < M) {
                float2 v;
                v.x = fmaxf(acc[mt][nt][0] + q0, 0.f);
                v.y = fmaxf(acc[mt][nt][1] + q1, 0.f);
                *(float2*)(out + (size_t)r0 * NN + c0) = v;
            }
            if (r0 + 8 < M) {
                float2 v;
                v.x = fmaxf(acc[mt][nt][2] + q0, 0.f);
                v.y = fmaxf(acc[mt][nt][3] + q1, 0.f);
                *(float2*)(out + (size_t)(r0 + 8) * NN + c0) = v;
            }
        }
    }
}

// logits[i] = bh2 + sum_j s[i][j] * Wh2[j]
__global__ void head_dot(const float* __restrict__ Wh2,
                         const float* __restrict__ bh2, float* __restrict__ out, int M) {
    int warp = (blockIdx.x * blockDim.x + threadIdx.x) >> 5;
    int lane = threadIdx.x & 31;
    if (warp >= M) return;
    float4 a = g_s[(size_t)warp * (HHID / 4) + lane];
    float b0 = Wh2[lane * 4 + 0], b1 = Wh2[lane * 4 + 1];
    float b2 = Wh2[lane * 4 + 2], b3 = Wh2[lane * 4 + 3];
    float v = a.x * b0 + a.y * b1 + a.z * b2 + a.w * b3;
    #pragma unroll
    for (int o = 16; o > 0; o >>= 1) v += __shfl_xor_sync(0xffffffffu, v, o);
    if (lane == 0) out[warp] = v + bh2[0];
}

// ---------------- launch -----------------------------------------------------
extern "C" void kernel_launch(void* const* d_in, const int* in_sizes, int n_in,
                              void* d_out, int out_size)
{
    const float* x   = (const float*)d_in[0];
    const void*  ei  = d_in[1];
    const float* q   = (const float*)d_in[2];
    const float* W1  = (const float*)d_in[3];
    const float* b1  = (const float*)d_in[4];
    const float* W2  = (const float*)d_in[5];
    const float* b2  = (const float*)d_in[6];
    const float* Wh1 = (const float*)d_in[7];
    const float* bh1 = (const float*)d_in[8];
    const float* Wh2 = (const float*)d_in[9];
    const float* bh2 = (const float*)d_in[10];
    float* out = (float*)d_out;

    const int M = in_sizes[0] / IN_DIM;   // 50000
    const int E = in_sizes[1] / 2;        // 400000

    float  *p_deg, *p_qb1, *p_qb2, *p_qbh;
    float4 *p_agg, *p_h1, *p_h2, *p_s;
    cudaGetSymbolAddress((void**)&p_deg, g_deg);
    cudaGetSymbolAddress((void**)&p_agg, g_agg);
    cudaGetSymbolAddress((void**)&p_h1,  g_h1);
    cudaGetSymbolAddress((void**)&p_h2,  g_h2);
    cudaGetSymbolAddress((void**)&p_s,   g_s);
    cudaGetSymbolAddress((void**)&p_qb1, g_qb1);
    cudaGetSymbolAddress((void**)&p_qb2, g_qb2);
    cudaGetSymbolAddress((void**)&p_qbh, g_qbh);

    detect_idx_dtype<<<1, 32>>>((const int*)ei);
    convert_idx<<<(2 * E + 255) / 256, 256>>>(ei, E);

    zero_deg    <<<(M + 255) / 256, 256>>>(M);
    count_deg   <<<(E + 255) / 256, 256>>>(E);
    finalize_deg<<<(M + 255) / 256, 256>>>(M);

    const int gx = (M + TBM - 1) / TBM;

    // ---- layer 1 ----
    copy_to_agg<<<(int)(((size_t)M * IN_DIM / 4 + 255) / 256), 256>>>(
        (const float4*)x, (size_t)M * IN_DIM / 4);
    scatter_add<<<(E + 7) / 8, 256>>>((const float4*)x, E, IN_DIM / 4);
    qproj<<<1, 256>>>(q, W1, b1, p_qb1, 2 * IN_DIM, QDIM, HID);
    gemm_cat_tc<IN_DIM, IN_DIM, HID><<<dim3(gx, HID / TBN), 256>>>(
        x, (const float*)p_agg, p_deg, W1, p_qb1, (float*)p_h1, M);

    // ---- layer 2 ----
    copy_to_agg<<<(int)(((size_t)M * HID / 4 + 255) / 256), 256>>>(
        (const float4*)p_h1, (size_t)M * HID / 4);
    scatter_add<<<(E + 7) / 8, 256>>>((const float4*)p_h1, E, HID / 4);
    qproj<<<1, 256>>>(q, W2, b2, p_qb2, 2 * HID, QDIM, HID);
    gemm_cat_tc<HID, HID, HID><<<dim3(gx, HID / TBN), 256>>>(
        (const float*)p_h1, (const float*)p_agg, p_deg, W2, p_qb2, (float*)p_h2, M);

    // ---- head ----
    qproj<<<1, 128>>>(q, Wh1, bh1, p_qbh, HID, QDIM, HHID);
    gemm_cat_tc<HID, 0, HHID><<<dim3(gx, HHID / TBN), 256>>>(
        (const float*)p_h2, nullptr, nullptr, Wh1, p_qbh, (float*)p_s, M);
    head_dot<<<(M * 32 + 255) / 256, 256>>>(Wh2, bh2, out, M);
}

// round 9
// speedup vs baseline: 2.8301x; 1.2004x over previous
#include <cuda_runtime.h>
#include <cuda_bf16.h>
#include <cstdint>
#include <cstddef>

#define N_NODES 50000
#define E_EDGES 400000
#define IN_DIM  384
#define HID     256
#define QDIM    384
#define HHID    128

// ---------------- scratch (static device globals) ----------------------------
__device__ float  g_deg[N_NODES];                            // 1/(deg+1)
__device__ float4 g_agg[(size_t)N_NODES * IN_DIM / 4];
__device__ float4 g_h1 [(size_t)N_NODES * HID / 4];
__device__ float4 g_h2 [(size_t)N_NODES * HID / 4];
__device__ float4 g_s  [(size_t)N_NODES * HHID / 4];
__device__ float  g_qb1[HID];
__device__ float  g_qb2[HID];
__device__ float  g_qbh[HHID];
__device__ int    g_is64;
__device__ int    g_src[E_EDGES];
__device__ int    g_dst[E_EDGES];
__device__ int    g_cnt[N_NODES];
__device__ int    g_fill[N_NODES];
__device__ int    g_rowptr[N_NODES + 1];
__device__ int    g_bsum[256];
__device__ int    g_eidx[E_EDGES];       // src ids grouped by dst (CSR)

// ---------------- edge-index dtype sniffing + conversion ---------------------
__global__ void detect_idx_dtype(const int* __restrict__ raw) {
    int nz = 0;
    for (int i = threadIdx.x; i < 128; i += 32)
        if (raw[2 * i + 1] != 0) nz = 1;
    #pragma unroll
    for (int o = 16; o > 0; o >>= 1) nz |= __shfl_xor_sync(0xffffffffu, nz, o);
    if (threadIdx.x == 0) g_is64 = nz ? 0 : 1;
}

__global__ void convert_idx(const void* __restrict__ raw, int E) {
    int i = blockIdx.x * blockDim.x + threadIdx.x;
    if (i >= 2 * E) return;
    int v;
    if (g_is64) v = (int)((const long long*)raw)[i];
    else        v = ((const int*)raw)[i];
    if ((unsigned)v >= (unsigned)N_NODES) v = 0;
    if (i < E) g_src[i] = v;
    else       g_dst[i - E] = v;
}

// ---------------- CSR build ---------------------------------------------------
__global__ void zero_cnt(int n) {
    int i = blockIdx.x * blockDim.x + threadIdx.x;
    if (i < n) { g_cnt[i] = 0; g_fill[i] = 0; }
}
__global__ void count_dst(int E) {
    int e = blockIdx.x * blockDim.x + threadIdx.x;
    if (e < E) atomicAdd(&g_cnt[g_dst[e]], 1);
}
// block-local exclusive scan (Hillis-Steele) + block totals
__global__ void scan1(int n) {
    __shared__ int sh[256];
    int i = blockIdx.x * 256 + threadIdx.x;
    int v = (i < n) ? g_cnt[i] : 0;
    sh[threadIdx.x] = v;
    __syncthreads();
    #pragma unroll
    for (int o = 1; o < 256; o <<= 1) {
        int t = (threadIdx.x >= o) ? sh[threadIdx.x - o] : 0;
        __syncthreads();
        sh[threadIdx.x] += t;
        __syncthreads();
    }
    if (i < n) g_rowptr[i] = sh[threadIdx.x] - v;   // exclusive within block
    if (threadIdx.x == 255) g_bsum[blockIdx.x] = sh[255];
}
__global__ void scan2(int nb) {
    __shared__ int sh[256];
    int v = (threadIdx.x < nb) ? g_bsum[threadIdx.x] : 0;
    sh[threadIdx.x] = v;
    __syncthreads();
    #pragma unroll
    for (int o = 1; o < 256; o <<= 1) {
        int t = (threadIdx.x >= o) ? sh[threadIdx.x - o] : 0;
        __syncthreads();
        sh[threadIdx.x] += t;
        __syncthreads();
    }
    if (threadIdx.x < nb) g_bsum[threadIdx.x] = sh[threadIdx.x] - v;  // exclusive
}
__global__ void scan3(int n, int E) {
    int i = blockIdx.x * blockDim.x + threadIdx.x;
    if (i < n) {
        g_rowptr[i] += g_bsum[i >> 8];
        g_deg[i] = 1.f / ((float)g_cnt[i] + 1.f);
    }
    if (i == 0) g_rowptr[n] = E;
}
__global__ void fill_csr(int E) {
    int e = blockIdx.x * blockDim.x + threadIdx.x;
    if (e >= E) return;
    int d = g_dst[e];
    int pos = g_rowptr[d] + atomicAdd(&g_fill[d], 1);
    g_eidx[pos] = g_src[e];
}

// ---------------- gather aggregation (no atomics) -----------------------------
// warp per node: agg[i] = h[i] + sum_{e in row i} h[eidx[e]]
template<int D4PL>   // float4 per lane: 3 for D=384, 2 for D=256
__global__ void gather_agg(const float4* __restrict__ feat, int M, int D4) {
    int node = (blockIdx.x * blockDim.x + threadIdx.x) >> 5;
    int lane = threadIdx.x & 31;
    if (node >= M) return;
    float4 acc[D4PL];
    const float4* hp = feat + (size_t)node * D4;
    #pragma unroll
    for (int j = 0; j < D4PL; ++j) acc[j] = hp[lane + 32 * j];
    int beg = g_rowptr[node], end = g_rowptr[node + 1];
    for (int e = beg; e < end; ++e) {
        const float4* sp = feat + (size_t)g_eidx[e] * D4;
        #pragma unroll
        for (int j = 0; j < D4PL; ++j) {
            float4 v = sp[lane + 32 * j];
            acc[j].x += v.x; acc[j].y += v.y; acc[j].z += v.z; acc[j].w += v.w;
        }
    }
    float4* dp = g_agg + (size_t)node * D4;
    #pragma unroll
    for (int j = 0; j < D4PL; ++j) dp[lane + 32 * j] = acc[j];
}

// qb[j] = b[j] + sum_k q[k] * W[(qoff+k)*N + j]
__global__ void qproj(const float* __restrict__ q, const float* __restrict__ W,
                      const float* __restrict__ b, float* __restrict__ qb,
                      int qoff, int qdim, int N) {
    int j = blockIdx.x * blockDim.x + threadIdx.x;
    if (j >= N) return;
    float acc = b[j];
    for (int k = 0; k < qdim; ++k)
        acc = fmaf(q[k], W[(size_t)(qoff + k) * N + j], acc);
    qb[j] = acc;
}

// ---------------- tensor-core concat GEMM (bf16x3 split) ---------------------
__device__ __forceinline__ void mma16816(float* d, const unsigned* a, const unsigned* b) {
    asm volatile("mma.sync.aligned.m16n8k16.row.col.f32.bf16.bf16.f32 "
                 "{%0,%1,%2,%3}, {%4,%5,%6,%7}, {%8,%9}, {%0,%1,%2,%3};"
                 : "+f"(d[0]), "+f"(d[1]), "+f"(d[2]), "+f"(d[3])
                 : "r"(a[0]), "r"(a[1]), "r"(a[2]), "r"(a[3]),
                   "r"(b[0]), "r"(b[1]));
}

__device__ __forceinline__ void split2(float x0, float x1, unsigned& hp, unsigned& lp) {
    __nv_bfloat16 h0 = __float2bfloat16_rn(x0);
    __nv_bfloat16 h1 = __float2bfloat16_rn(x1);
    __nv_bfloat16 l0 = __float2bfloat16_rn(x0 - __bfloat162float(h0));
    __nv_bfloat16 l1 = __float2bfloat16_rn(x1 - __bfloat162float(h1));
    hp = (unsigned)__bfloat16_as_ushort(h0) | ((unsigned)__bfloat16_as_ushort(h1) << 16);
    lp = (unsigned)__bfloat16_as_ushort(l0) | ((unsigned)__bfloat16_as_ushort(l1) << 16);
}

#define TBM 128
#define TBN 64
#define TBK 32
#define SPAD 34

template<int K1, int K2, int NN>
__global__ __launch_bounds__(256)
void gemm_cat_tc(const float* __restrict__ A1,
                 const float* __restrict__ A2,
                 const float* __restrict__ rscale,
                 const float* __restrict__ W,
                 const float* __restrict__ qb,
                 float* __restrict__ out, int M)
{
    __shared__ unsigned short As_h[TBM][SPAD];
    __shared__ unsigned short As_l[TBM][SPAD];
    __shared__ unsigned short Bs_h[TBN][SPAD];   // transposed: [n][k]
    __shared__ unsigned short Bs_l[TBN][SPAD];

    const int tid  = threadIdx.x;
    const int lane = tid & 31;
    const int wid  = tid >> 5;
    const int wm   = wid & 3;
    const int wn   = wid >> 2;
    const int block_row = blockIdx.x * TBM;
    const int block_col = blockIdx.y * TBN;

    int a_row[4], a_k[4];
    bool a_ok[4];
    float a_rs[4];
    #pragma unroll
    for (int i = 0; i < 4; ++i) {
        int idx = i * 256 + tid;
        a_row[i] = idx >> 3;
        a_k[i]   = (idx & 7) * 4;
        int gr = block_row + a_row[i];
        a_ok[i] = gr < M;
        a_rs[i] = (K2 > 0 && a_ok[i]) ? rscale[gr] : 1.f;
    }
    int b_k[2], b_n[2];
    #pragma unroll
    for (int i = 0; i < 2; ++i) {
        int idx = i * 256 + tid;
        b_k[i] = idx >> 4;
        b_n[i] = (idx & 15) * 4;
    }

    float4 aF[4], bF[2];
    const int KTOT = K1 + K2;
    const int NSTEP = KTOT / TBK;

    auto loadTiles = [&](int kt) {
        const int kbase = kt * TBK;
        const bool inA1 = kbase < K1;
        #pragma unroll
        for (int i = 0; i < 4; ++i) {
            if (a_ok[i]) {
                int gr = block_row + a_row[i];
                if (inA1) {
                    aF[i] = *(const float4*)(A1 + (size_t)gr * K1 + kbase + a_k[i]);
                } else {
                    float4 v = *(const float4*)(A2 + (size_t)gr * K2 + (kbase - K1) + a_k[i]);
                    float rs = a_rs[i];
                    v.x *= rs; v.y *= rs; v.z *= rs; v.w *= rs;
                    aF[i] = v;
                }
            } else {
                aF[i] = make_float4(0.f, 0.f, 0.f, 0.f);
            }
        }
        #pragma unroll
        for (int i = 0; i < 2; ++i) {
            bF[i] = *(const float4*)(W + (size_t)(kbase + b_k[i]) * NN + block_col + b_n[i]);
        }
    };

    auto storeTiles = [&]() {
        #pragma unroll
        for (int i = 0; i < 4; ++i) {
            unsigned h0, l0, h1, l1;
            split2(aF[i].x, aF[i].y, h0, l0);
            split2(aF[i].z, aF[i].w, h1, l1);
            *(unsigned*)&As_h[a_row[i]][a_k[i]]     = h0;
            *(unsigned*)&As_h[a_row[i]][a_k[i] + 2] = h1;
            *(unsigned*)&As_l[a_row[i]][a_k[i]]     = l0;
            *(unsigned*)&As_l[a_row[i]][a_k[i] + 2] = l1;
        }
        #pragma unroll
        for (int i = 0; i < 2; ++i) {
            float v[4] = {bF[i].x, bF[i].y, bF[i].z, bF[i].w};
            #pragma unroll
            for (int j = 0; j < 4; ++j) {
                __nv_bfloat16 h = __float2bfloat16_rn(v[j]);
                __nv_bfloat16 l = __float2bfloat16_rn(v[j] - __bfloat162float(h));
                Bs_h[b_n[i] + j][b_k[i]] = __bfloat16_as_ushort(h);
                Bs_l[b_n[i] + j][b_k[i]] = __bfloat16_as_ushort(l);
            }
        }
    };

    float acc[2][4][4];
    #pragma unroll
    for (int mt = 0; mt < 2; ++mt)
        #pragma unroll
        for (int nt = 0; nt < 4; ++nt)
            #pragma unroll
            for (int r = 0; r < 4; ++r) acc[mt][nt][r] = 0.f;

    const int grp = lane >> 2;
    const int tig = lane & 3;

    loadTiles(0);
    for (int kt = 0; kt < NSTEP; ++kt) {
        storeTiles();
        __syncthreads();
        if (kt + 1 < NSTEP) loadTiles(kt + 1);

        #pragma unroll
        for (int kk = 0; kk < 2; ++kk) {
            const int c = kk * 16 + tig * 2;
            unsigned ah[2][4], al[2][4], bh[4][2], bl[4][2];
            #pragma unroll
            for (int mt = 0; mt < 2; ++mt) {
                int r = wm * 32 + mt * 16 + grp;
                ah[mt][0] = *(const unsigned*)&As_h[r][c];
                ah[mt][1] = *(const unsigned*)&As_h[r + 8][c];
                ah[mt][2] = *(const unsigned*)&As_h[r][c + 8];
                ah[mt][3] = *(const unsigned*)&As_h[r + 8][c + 8];
                al[mt][0] = *(const unsigned*)&As_l[r][c];
                al[mt][1] = *(const unsigned*)&As_l[r + 8][c];
                al[mt][2] = *(const unsigned*)&As_l[r][c + 8];
                al[mt][3] = *(const unsigned*)&As_l[r + 8][c + 8];
            }
            #pragma unroll
            for (int nt = 0; nt < 4; ++nt) {
                int n = wn * 32 + nt * 8 + grp;
                bh[nt][0] = *(const unsigned*)&Bs_h[n][c];
                bh[nt][1] = *(const unsigned*)&Bs_h[n][c + 8];
                bl[nt][0] = *(const unsigned*)&Bs_l[n][c];
                bl[nt][1] = *(const unsigned*)&Bs_l[n][c + 8];
            }
            #pragma unroll
            for (int mt = 0; mt < 2; ++mt)
                #pragma unroll
                for (int nt = 0; nt < 4; ++nt) {
                    mma16816(acc[mt][nt], ah[mt], bh[nt]);
                    mma16816(acc[mt][nt], ah[mt], bl[nt]);
                    mma16816(acc[mt][nt], al[mt], bh[nt]);
                }
        }
        __syncthreads();
    }

    #pragma unroll
    for (int mt = 0; mt < 2; ++mt) {
        #pragma unroll
        for (int nt = 0; nt < 4; ++nt) {
            int r0 = block_row + wm * 32 + mt * 16 + grp;
            int c0 = block_col + wn * 32 + nt * 8 + tig * 2;
            float q0 = qb[c0], q1 = qb[c0 + 1];
            if (r0 < M) {
                float2 v;
                v.x = fmaxf(acc[mt][nt][0] + q0, 0.f);
                v.y = fmaxf(acc[mt][nt][1] + q1, 0.f);
                *(float2*)(out + (size_t)r0 * NN + c0) = v;
            }
            if (r0 + 8 < M) {
                float2 v;
                v.x = fmaxf(acc[mt][nt][2] + q0, 0.f);
                v.y = fmaxf(acc[mt][nt][3] + q1, 0.f);
                *(float2*)(out + (size_t)(r0 + 8) * NN + c0) = v;
            }
        }
    }
}

// logits[i] = bh2 + sum_j s[i][j] * Wh2[j]
__global__ void head_dot(const float* __restrict__ Wh2,
                         const float* __restrict__ bh2, float* __restrict__ out, int M) {
    int warp = (blockIdx.x * blockDim.x + threadIdx.x) >> 5;
    int lane = threadIdx.x & 31;
    if (warp >= M) return;
    float4 a = g_s[(size_t)warp * (HHID / 4) + lane];
    float b0 = Wh2[lane * 4 + 0], b1 = Wh2[lane * 4 + 1];
    float b2 = Wh2[lane * 4 + 2], b3 = Wh2[lane * 4 + 3];
    float v = a.x * b0 + a.y * b1 + a.z * b2 + a.w * b3;
    #pragma unroll
    for (int o = 16; o > 0; o >>= 1) v += __shfl_xor_sync(0xffffffffu, v, o);
    if (lane == 0) out[warp] = v + bh2[0];
}

// ---------------- launch -----------------------------------------------------
extern "C" void kernel_launch(void* const* d_in, const int* in_sizes, int n_in,
                              void* d_out, int out_size)
{
    const float* x   = (const float*)d_in[0];
    const void*  ei  = d_in[1];
    const float* q   = (const float*)d_in[2];
    const float* W1  = (const float*)d_in[3];
    const float* b1  = (const float*)d_in[4];
    const float* W2  = (const float*)d_in[5];
    const float* b2  = (const float*)d_in[6];
    const float* Wh1 = (const float*)d_in[7];
    const float* bh1 = (const float*)d_in[8];
    const float* Wh2 = (const float*)d_in[9];
    const float* bh2 = (const float*)d_in[10];
    float* out = (float*)d_out;

    const int M = in_sizes[0] / IN_DIM;   // 50000
    const int E = in_sizes[1] / 2;        // 400000

    float  *p_deg, *p_qb1, *p_qb2, *p_qbh;
    float4 *p_agg, *p_h1, *p_h2, *p_s;
    cudaGetSymbolAddress((void**)&p_deg, g_deg);
    cudaGetSymbolAddress((void**)&p_agg, g_agg);
    cudaGetSymbolAddress((void**)&p_h1,  g_h1);
    cudaGetSymbolAddress((void**)&p_h2,  g_h2);
    cudaGetSymbolAddress((void**)&p_s,   g_s);
    cudaGetSymbolAddress((void**)&p_qb1, g_qb1);
    cudaGetSymbolAddress((void**)&p_qb2, g_qb2);
    cudaGetSymbolAddress((void**)&p_qbh, g_qbh);

    const int nb = (M + 255) / 256;       // scan blocks (196)

    detect_idx_dtype<<<1, 32>>>((const int*)ei);
    convert_idx<<<(2 * E + 255) / 256, 256>>>(ei, E);

    // CSR build: counts -> exclusive scan -> fill
    zero_cnt <<<nb, 256>>>(M);
    count_dst<<<(E + 255) / 256, 256>>>(E);
    scan1    <<<nb, 256>>>(M);
    scan2    <<<1, 256>>>(nb);
    scan3    <<<nb, 256>>>(M, E);
    fill_csr <<<(E + 255) / 256, 256>>>(E);

    const int gx = (M + TBM - 1) / TBM;
    const int gwarp = (M * 32 + 255) / 256;

    // ---- layer 1 ----
    gather_agg<3><<<gwarp, 256>>>((const float4*)x, M, IN_DIM / 4);
    qproj<<<1, 256>>>(q, W1, b1, p_qb1, 2 * IN_DIM, QDIM, HID);
    gemm_cat_tc<IN_DIM, IN_DIM, HID><<<dim3(gx, HID / TBN), 256>>>(
        x, (const float*)p_agg, p_deg, W1, p_qb1, (float*)p_h1, M);

    // ---- layer 2 ----
    gather_agg<2><<<gwarp, 256>>>((const float4*)p_h1, M, HID / 4);
    qproj<<<1, 256>>>(q, W2, b2, p_qb2, 2 * HID, QDIM, HID);
    gemm_cat_tc<HID, HID, HID><<<dim3(gx, HID / TBN), 256>>>(
        (const float*)p_h1, (const float*)p_agg, p_deg, W2, p_qb2, (float*)p_h2, M);

    // ---- head ----
    qproj<<<1, 128>>>(q, Wh1, bh1, p_qbh, HID, QDIM, HHID);
    gemm_cat_tc<HID, 0, HHID><<<dim3(gx, HHID / TBN), 256>>>(
        (const float*)p_h2, nullptr, nullptr, Wh1, p_qbh, (float*)p_s, M);
    head_dot<<<gwarp, 256>>>(Wh2, bh2, out, M);
}